// round 3
// baseline (speedup 1.0000x reference)
#include <cuda_runtime.h>

// EMA alpha=0.2; out[i] = e_{idx}, idx = max(len[i],1)-1.
// Truncated 64-tap trailing window (tail weight 0.8^63 ~ 8e-7 << 1e-3 threshold).
//
// Layout: 16 lanes per row, 2 rows per warp -> 8192 warps total = 55 warps/SM
// -> SINGLE wave on 148 SMs (vs 1.73 waves at one warp/row).
// Each lane does ONE aligned LDG.128 (float4): window start aligned up to 4,
// clamped to T-64 so the 64-float window stays inside the row. Align-up keeps
// s >= n-63, so all taps with weight > 0.8^63 are included.
// One exp2f per lane; the other 3 weights are derived by constant multiplies.

#define LOG2_08 (-0.32192809488736234787f) // log2(0.8)

__global__ void __launch_bounds__(256)
ema_last_kernel(const float* __restrict__ x,
                const int* __restrict__ valid_len,
                float* __restrict__ out,
                int B, int T)
{
    int warp    = (int)((blockIdx.x * blockDim.x + threadIdx.x) >> 5);
    int lane    = threadIdx.x & 31;
    int sub     = lane & 15;            // lane within 16-lane row group
    int row     = warp * 2 + (lane >> 4);
    if (row >= B) return;

    int len = valid_len[row];
    int n   = (len > 1 ? len : 1) - 1;  // target index idx = L-1

    // Aligned window start: s in [n-63, n-60] (or 0 for short rows), 4-aligned,
    // clamped so [s, s+63] stays inside the row.
    int s = n - 63;
    s = (s > 0) ? ((s + 3) & ~3) : 0;
    if (s > T - 64) s = T - 64;

    // One aligned 16B load per lane: 16 lanes cover the 64-float window.
    const float4 v = reinterpret_cast<const float4*>(x + (size_t)row * (size_t)T + s)[sub];

    int j0 = s + 4 * sub;               // global index of v.x
    // base weight for j0 (tap form): 0.2 * 0.8^(n - j0)
    float wb = 0.2f * exp2f((float)(n - j0) * LOG2_08);

    // w_k = wb * 0.8^{-k}
    float w0 = wb;
    float w1 = wb * 1.25f;
    float w2 = wb * 1.5625f;
    float w3 = wb * 1.953125f;

    // seed tap (j==0) has coefficient 0.8^n = 5 * (0.2*0.8^n); taps past n get 0.
    if (j0 + 0 == 0) w0 *= 5.0f;   if (j0 + 0 > n) w0 = 0.0f;
    if (j0 + 1 == 0) w1 *= 5.0f;   if (j0 + 1 > n) w1 = 0.0f;
    if (j0 + 2 == 0) w2 *= 5.0f;   if (j0 + 2 > n) w2 = 0.0f;
    if (j0 + 3 == 0) w3 *= 5.0f;   if (j0 + 3 > n) w3 = 0.0f;

    float acc = fmaf(w0, v.x, fmaf(w1, v.y, fmaf(w2, v.z, w3 * v.w)));

    // reduce over the 16-lane group (xor offsets stay within the group)
#pragma unroll
    for (int off = 8; off > 0; off >>= 1)
        acc += __shfl_xor_sync(0xffffffffu, acc, off);

    if (sub == 0) out[row] = acc;
}

extern "C" void kernel_launch(void* const* d_in, const int* in_sizes, int n_in,
                              void* d_out, int out_size)
{
    const float* pop_history = (const float*)d_in[0];
    const int*   valid_len   = (const int*)d_in[1];
    float*       out         = (float*)d_out;

    int B = in_sizes[1];               // 16384
    int T = in_sizes[0] / in_sizes[1]; // 2048

    int threads = 256;                 // 8 warps = 16 rows per block
    int rows_per_block = (threads / 32) * 2;
    int blocks = (B + rows_per_block - 1) / rows_per_block;   // 1024
    ema_last_kernel<<<blocks, threads>>>(pop_history, valid_len, out, B, T);
}